// round 2
// baseline (speedup 1.0000x reference)
#include <cuda_runtime.h>

// Problem constants (fixed by the dataset)
#define NJ    25      // joints
#define CIN   256     // in features
#define HID   128     // hidden = H//2
#define YPAD  132     // padded row stride for sY (bank-conflict-free phase 3)

// out[b,i,j] = c1*(z[j]-z[i]) + c2 * sum_h W2[h]*|y[b,j,h]-y[b,i,h]|
//   y = src @ W1^T   (telescoped path sum + linearity of W1)
//   z[n] = sum_h W2[h]*y[n,h]
//   c1=(1+alpha)/2, c2=(1-alpha)/2  (PReLU = linear + abs decomposition)

__global__ __launch_bounds__(256, 2)
void fused_edge_mlp_kernel(const float* __restrict__ src,
                           const float* __restrict__ W1,
                           const float* __restrict__ alpha_p,
                           const float* __restrict__ W2,
                           float* __restrict__ out)
{
    __shared__ float sSrc[NJ * CIN];   // 25.6 KB
    __shared__ float sY[NJ * YPAD];    // 13.2 KB (padded: stride 132 floats)
    __shared__ float sW2[HID];
    __shared__ float sZ[NJ];

    const int tid = threadIdx.x;
    const int b   = blockIdx.x;
    const float* srcB = src + (size_t)b * (NJ * CIN);

    // ---- Phase 1: stage src[b] (coalesced float4) + W2 ----
    {
        const float4* g4 = reinterpret_cast<const float4*>(srcB);
        float4*       s4 = reinterpret_cast<float4*>(sSrc);
        #pragma unroll
        for (int idx = tid; idx < NJ * CIN / 4; idx += 256)
            s4[idx] = g4[idx];
        if (tid < HID) sW2[tid] = W2[tid];
    }
    __syncthreads();

    // ---- Phase 2: y[n][h] = dot(src[n,:], W1[h,:]) ----
    // Thread tiling: hq = tid&31 owns 4 h-rows (h0..h0+3); ng = tid>>5 owns
    // n in {ng, ng+8, ng+16, ng+24}. Register tile 4h x up-to-4n => 16 acc.
    // W1 rows stay in registers across the n's => W1 read 8x/block, not 25x.
    {
        const int hq = tid & 31;
        const int ng = tid >> 5;     // warp id: n-set is warp-uniform
        const int h0 = hq << 2;

        float acc[4][4];
        #pragma unroll
        for (int a = 0; a < 4; a++)
            #pragma unroll
            for (int k = 0; k < 4; k++) acc[a][k] = 0.0f;

        const float4* wr0 = reinterpret_cast<const float4*>(W1 + (h0 + 0) * CIN);
        const float4* wr1 = reinterpret_cast<const float4*>(W1 + (h0 + 1) * CIN);
        const float4* wr2 = reinterpret_cast<const float4*>(W1 + (h0 + 2) * CIN);
        const float4* wr3 = reinterpret_cast<const float4*>(W1 + (h0 + 3) * CIN);

        #pragma unroll 4
        for (int c4 = 0; c4 < CIN / 4; c4++) {
            const float4 w0 = wr0[c4];
            const float4 w1 = wr1[c4];
            const float4 w2 = wr2[c4];
            const float4 w3 = wr3[c4];
            #pragma unroll
            for (int a = 0; a < 4; a++) {
                const int n = ng + (a << 3);
                if (n < NJ) {   // warp-uniform predicate
                    const float4 s = reinterpret_cast<const float4*>(sSrc + n * CIN)[c4];
                    acc[a][0] += s.x * w0.x + s.y * w0.y + s.z * w0.z + s.w * w0.w;
                    acc[a][1] += s.x * w1.x + s.y * w1.y + s.z * w1.z + s.w * w1.w;
                    acc[a][2] += s.x * w2.x + s.y * w2.y + s.z * w2.z + s.w * w2.w;
                    acc[a][3] += s.x * w3.x + s.y * w3.y + s.z * w3.z + s.w * w3.w;
                }
            }
        }
        #pragma unroll
        for (int a = 0; a < 4; a++) {
            const int n = ng + (a << 3);
            if (n < NJ) {
                sY[n * YPAD + h0 + 0] = acc[a][0];
                sY[n * YPAD + h0 + 1] = acc[a][1];
                sY[n * YPAD + h0 + 2] = acc[a][2];
                sY[n * YPAD + h0 + 3] = acc[a][3];
            }
        }
    }
    __syncthreads();

    // ---- Phase 2.5: z[n] = sum_h W2[h]*y[n][h]  (one warp per n) ----
    {
        const int warp = tid >> 5, lane = tid & 31;
        for (int n = warp; n < NJ; n += 8) {
            const float* yr = sY + n * YPAD;
            float v = sW2[lane]      * yr[lane]
                    + sW2[lane + 32] * yr[lane + 32]
                    + sW2[lane + 64] * yr[lane + 64]
                    + sW2[lane + 96] * yr[lane + 96];
            #pragma unroll
            for (int o = 16; o > 0; o >>= 1)
                v += __shfl_xor_sync(0xffffffffu, v, o);
            if (lane == 0) sZ[n] = v;
        }
    }
    __syncthreads();

    // ---- Phase 3: out[i,j] = c1*(z[j]-z[i]) + c2*sum_h w2[h]*|yj-yi| ----
    {
        const float alpha = alpha_p[0];
        const float c1 = 0.5f * (1.0f + alpha);
        const float c2 = 0.5f * (1.0f - alpha);
        float* outB = out + (size_t)b * (NJ * NJ);

        for (int p = tid; p < NJ * NJ; p += 256) {
            const int i = p / NJ;
            const int j = p - i * NJ;
            const float* yi = sY + i * YPAD;
            const float* yj = sY + j * YPAD;
            float acc = 0.0f;
            #pragma unroll 8
            for (int h = 0; h < HID; h += 4) {
                const float4 a  = *reinterpret_cast<const float4*>(yj + h);
                const float4 bb = *reinterpret_cast<const float4*>(yi + h);
                const float4 w  = *reinterpret_cast<const float4*>(sW2 + h);
                acc += w.x * fabsf(a.x - bb.x);
                acc += w.y * fabsf(a.y - bb.y);
                acc += w.z * fabsf(a.z - bb.z);
                acc += w.w * fabsf(a.w - bb.w);
            }
            outB[p] = c1 * (sZ[j] - sZ[i]) + c2 * acc;
        }
    }
}

extern "C" void kernel_launch(void* const* d_in, const int* in_sizes, int n_in,
                              void* d_out, int out_size)
{
    // metadata order: src, heads, ends, pair_ids, W1, alpha, W2
    const float* src   = (const float*)d_in[0];
    const float* W1    = (const float*)d_in[4];
    const float* alpha = (const float*)d_in[5];
    const float* W2    = (const float*)d_in[6];
    float* out = (float*)d_out;

    const int batch = in_sizes[0] / (NJ * CIN);   // 256
    fused_edge_mlp_kernel<<<batch, 256>>>(src, W1, alpha, W2, out);
}

// round 3
// speedup vs baseline: 2.8059x; 2.8059x over previous
#include <cuda_runtime.h>

// Problem constants (fixed by the dataset)
#define NJ     25      // joints
#define CIN    256     // in features
#define HID    128     // hidden = H//2
#define BPAD   36      // padded row (floats) for staged W1 chunk [h][36]
#define YPAD   132     // padded row (floats) for sY
#define NCHUNK 8
#define CCH    32      // c-columns per W1 chunk

typedef unsigned long long ull;

// packed dual-fp32 FMA: d = a*b + d (lane-wise on (lo,hi))
__device__ __forceinline__ void fma2(ull& d, ull a, ull b) {
    asm("fma.rn.f32x2 %0, %1, %2, %0;" : "+l"(d) : "l"(a), "l"(b));
}
__device__ __forceinline__ float lo2(ull v){ return __uint_as_float((unsigned)v); }
__device__ __forceinline__ float hi2(ull v){ return __uint_as_float((unsigned)(v >> 32)); }

// out[b,i,j] = c1*(z[j]-z[i]) + c2 * sum_h W2[h]*|y[b,j,h]-y[b,i,h]|
//   y = src @ W1^T  (chain-path telescoping + linearity of W1)
//   z[n] = sum_h W2[h]*y[n,h];  c1=(1+a)/2, c2=(1-a)/2 (PReLU = linear + abs)

__global__ __launch_bounds__(256, 2)
void fused_edge_mlp_kernel(const float* __restrict__ src,
                           const float* __restrict__ W1,
                           const float* __restrict__ alpha_p,
                           const float* __restrict__ W2,
                           float* __restrict__ out)
{
    __shared__ float sSrc[NJ * CIN];      // 25.6 KB
    __shared__ float sBY[HID * BPAD];     // 18.4 KB: W1 chunk buffer, reused as sY
    __shared__ float sW2[HID];
    __shared__ float sZ[NJ];

    const int tid = threadIdx.x;
    const int b   = blockIdx.x;

    // ---- Phase 1: stage src[b] (coalesced) + W2 ----
    {
        const float4* g4 = reinterpret_cast<const float4*>(src + (size_t)b * NJ * CIN);
        float4*       s4 = reinterpret_cast<float4*>(sSrc);
        for (int i = tid; i < NJ * CIN / 4; i += 256) s4[i] = g4[i];
        if (tid < HID) sW2[tid] = W2[tid];
    }

    // ---- Phase 2: y[n][h] = dot(src[n,:], W1[h,:]) via chunked smem W1 ----
    // warp w owns h in [16w, 16w+16): lane owns hA = 16w + (lane&7) and hA+8.
    // lane-group g = lane>>3 owns n in [7g, 7g+7) (last group: 4).
    // All smem loads: s = warp-phase-uniform broadcast; w = stride-36 rows,
    // conflict-free. f32x2 packs pairs of consecutive c (no pack instrs).
    const int lane = tid & 31, warp = tid >> 5;
    const int hA = warp * 16 + (lane & 7);
    const int g  = lane >> 3;
    const int n0 = g * 7;

    ull accA[7], accB[7];
    #pragma unroll
    for (int k = 0; k < 7; k++) { accA[k] = 0ull; accB[k] = 0ull; }

    // W1 staging addresses: thread loads row (tid>>3)+32*it, cols 4*(tid&7)..+3
    const int whr = tid >> 3;
    const int wcc = (tid & 7) * 4;
    const float* W1base = W1 + (size_t)whr * CIN + wcc;

    float4 pf[4];                         // register prefetch of next chunk
    #pragma unroll
    for (int it = 0; it < 4; it++)
        pf[it] = *reinterpret_cast<const float4*>(W1base + (size_t)it * 32 * CIN);

    #pragma unroll 1
    for (int ch = 0; ch < NCHUNK; ch++) {
        __syncthreads();   // previous chunk's reads done (and phase-1 stores visible)
        #pragma unroll
        for (int it = 0; it < 4; it++)
            *reinterpret_cast<float4*>(sBY + (whr + it * 32) * BPAD + wcc) = pf[it];
        if (ch + 1 < NCHUNK) {
            #pragma unroll
            for (int it = 0; it < 4; it++)
                pf[it] = *reinterpret_cast<const float4*>(W1base + (size_t)it * 32 * CIN
                                                          + (ch + 1) * CCH);
        }
        __syncthreads();   // chunk visible

        const float* sA  = sSrc + n0 * CIN + ch * CCH;
        const float* wPA = sBY + hA * BPAD;
        #pragma unroll
        for (int c4 = 0; c4 < CCH / 4; c4++) {
            const ulonglong2 wa = *reinterpret_cast<const ulonglong2*>(wPA + c4 * 4);
            const ulonglong2 wb = *reinterpret_cast<const ulonglong2*>(wPA + 8 * BPAD + c4 * 4);
            #pragma unroll
            for (int k = 0; k < 7; k++) {
                if (g < 3 || k < 4) {     // n-slot valid (phase-uniform)
                    const ulonglong2 s2 =
                        *reinterpret_cast<const ulonglong2*>(sA + k * CIN + c4 * 4);
                    fma2(accA[k], s2.x, wa.x);
                    fma2(accA[k], s2.y, wa.y);
                    fma2(accB[k], s2.x, wb.x);
                    fma2(accB[k], s2.y, wb.y);
                }
            }
        }
    }

    __syncthreads();       // done reading sBY as W1 -> reuse region as sY
    float* sY = sBY;
    #pragma unroll
    for (int k = 0; k < 7; k++) {
        if (g < 3 || k < 4) {
            const int n = n0 + k;
            sY[n * YPAD + hA]     = lo2(accA[k]) + hi2(accA[k]);
            sY[n * YPAD + hA + 8] = lo2(accB[k]) + hi2(accB[k]);
        }
    }
    __syncthreads();

    // ---- Phase 2.5: z[n] = sum_h W2[h]*y[n][h] (warp per n) ----
    for (int n = warp; n < NJ; n += 8) {
        const float* yr = sY + n * YPAD;
        float v = sW2[lane]      * yr[lane]
                + sW2[lane + 32] * yr[lane + 32]
                + sW2[lane + 64] * yr[lane + 64]
                + sW2[lane + 96] * yr[lane + 96];
        #pragma unroll
        for (int o = 16; o > 0; o >>= 1)
            v += __shfl_xor_sync(0xffffffffu, v, o);
        if (lane == 0) sZ[n] = v;
    }
    __syncthreads();

    // ---- Phase 3: 2x2 (i,j) register tiles, f32x2 math ----
    if (tid < 169) {                       // 13x13 tiles cover 25x25 (padded 26)
        const float alpha = alpha_p[0];
        const float c1 = 0.5f * (1.0f + alpha);
        const float c2 = 0.5f * (1.0f - alpha);
        const int ti = tid / 13, tj = tid - ti * 13;
        const int i0 = 2 * ti, j0 = 2 * tj;

        const ull NEG1  = 0xBF800000BF800000ull;   // (-1.0f, -1.0f)
        const ull AMASK = 0x7FFFFFFF7FFFFFFFull;   // abs mask

        ull a00 = 0, a01 = 0, a10 = 0, a11 = 0;
        const float* pi0 = sY + i0 * YPAD;
        const float* pj0 = sY + j0 * YPAD;

        #pragma unroll 8
        for (int h = 0; h < HID; h += 4) {
            const ulonglong2 w   = *reinterpret_cast<const ulonglong2*>(sW2 + h);
            const ulonglong2 vi0 = *reinterpret_cast<const ulonglong2*>(pi0 + h);
            const ulonglong2 vi1 = *reinterpret_cast<const ulonglong2*>(pi0 + YPAD + h);
            const ulonglong2 vj0 = *reinterpret_cast<const ulonglong2*>(pj0 + h);
            const ulonglong2 vj1 = *reinterpret_cast<const ulonglong2*>(pj0 + YPAD + h);
            ull d;
            // (0,0)
            d = vj0.x; fma2(d, vi0.x, NEG1); d &= AMASK; fma2(a00, d, w.x);
            d = vj0.y; fma2(d, vi0.y, NEG1); d &= AMASK; fma2(a00, d, w.y);
            // (0,1)
            d = vj1.x; fma2(d, vi0.x, NEG1); d &= AMASK; fma2(a01, d, w.x);
            d = vj1.y; fma2(d, vi0.y, NEG1); d &= AMASK; fma2(a01, d, w.y);
            // (1,0)
            d = vj0.x; fma2(d, vi1.x, NEG1); d &= AMASK; fma2(a10, d, w.x);
            d = vj0.y; fma2(d, vi1.y, NEG1); d &= AMASK; fma2(a10, d, w.y);
            // (1,1)
            d = vj1.x; fma2(d, vi1.x, NEG1); d &= AMASK; fma2(a11, d, w.x);
            d = vj1.y; fma2(d, vi1.y, NEG1); d &= AMASK; fma2(a11, d, w.y);
        }

        float* outB = out + (size_t)b * NJ * NJ;
        const int i1 = i0 + 1, j1 = j0 + 1;
        outB[i0 * NJ + j0] = c1 * (sZ[j0] - sZ[i0]) + c2 * (lo2(a00) + hi2(a00));
        if (j1 < NJ)
            outB[i0 * NJ + j1] = c1 * (sZ[j1] - sZ[i0]) + c2 * (lo2(a01) + hi2(a01));
        if (i1 < NJ) {
            outB[i1 * NJ + j0] = c1 * (sZ[j0] - sZ[i1]) + c2 * (lo2(a10) + hi2(a10));
            if (j1 < NJ)
                outB[i1 * NJ + j1] = c1 * (sZ[j1] - sZ[i1]) + c2 * (lo2(a11) + hi2(a11));
        }
    }
}

extern "C" void kernel_launch(void* const* d_in, const int* in_sizes, int n_in,
                              void* d_out, int out_size)
{
    // metadata order: src, heads, ends, pair_ids, W1, alpha, W2
    const float* src   = (const float*)d_in[0];
    const float* W1    = (const float*)d_in[4];
    const float* alpha = (const float*)d_in[5];
    const float* W2    = (const float*)d_in[6];
    float* out = (float*)d_out;

    const int batch = in_sizes[0] / (NJ * CIN);   // 256
    fused_edge_mlp_kernel<<<batch, 256>>>(src, W1, alpha, W2, out);
}

// round 4
// speedup vs baseline: 3.2380x; 1.1540x over previous
#include <cuda_runtime.h>

// Problem constants (fixed by the dataset)
#define NJ     25      // joints
#define CIN    256     // in features
#define SPAD   260     // padded sSrc row stride (floats): breaks 4-way bank conflict
#define HID    128     // hidden = H//2
#define BPAD   36      // padded row (floats) for staged W1 chunk [h][36]
#define YPAD   132     // padded row (floats) for sY
#define NCHUNK 8
#define CCH    32      // c-columns per W1 chunk

typedef unsigned long long ull;

// packed dual-fp32 FMA: d = a*b + d (lane-wise on (lo,hi))
__device__ __forceinline__ void fma2(ull& d, ull a, ull b) {
    asm("fma.rn.f32x2 %0, %1, %2, %0;" : "+l"(d) : "l"(a), "l"(b));
}
__device__ __forceinline__ float lo2(ull v){ return __uint_as_float((unsigned)v); }
__device__ __forceinline__ float hi2(ull v){ return __uint_as_float((unsigned)(v >> 32)); }

// out[b,i,j] = c1*(z[j]-z[i]) + c2 * sum_h W2[h]*|y[b,j,h]-y[b,i,h]|
//   y = src @ W1^T  (chain-path telescoping + linearity of W1)
//   z[n] = sum_h W2[h]*y[n,h];  c1=(1+a)/2, c2=(1-a)/2 (PReLU = linear + abs)

__global__ __launch_bounds__(256, 2)
void fused_edge_mlp_kernel(const float* __restrict__ src,
                           const float* __restrict__ W1,
                           const float* __restrict__ alpha_p,
                           const float* __restrict__ W2,
                           float* __restrict__ out)
{
    __shared__ float sSrc[NJ * SPAD];     // 26.0 KB (padded rows)
    __shared__ float sBY[HID * BPAD];     // 18.4 KB: W1 chunk buffer, reused as sY
    __shared__ float sW2[HID];
    __shared__ float sZ[NJ];

    const int tid = threadIdx.x;
    const int b   = blockIdx.x;

    // ---- Phase 1: stage src[b] (coalesced loads, padded stores) + W2 ----
    {
        const float4* g4 = reinterpret_cast<const float4*>(src + (size_t)b * NJ * CIN);
        for (int i = tid; i < NJ * CIN / 4; i += 256) {
            const int n = i >> 6;            // 64 float4 per row
            const int c = i & 63;
            *reinterpret_cast<float4*>(sSrc + n * SPAD + c * 4) = g4[i];
        }
        if (tid < HID) sW2[tid] = W2[tid];
    }

    // ---- Phase 2: y[n][h] = dot(src[n,:], W1[h,:]) via chunked smem W1 ----
    // warp w owns h in [16w, 16w+16): lane owns hA = 16w + (lane&7) and hA+8.
    // lane-group g = lane>>3 owns n in [7g, 7g+7) (last group: 4).
    // w-rows stride 36 floats: banks shift 4/row -> conflict-free.
    // s-rows stride 260 floats: concurrent n (spacing 7) at bank offsets
    // {0,28,20,12} -> conflict-free broadcast. f32x2 packs consecutive c.
    const int lane = tid & 31, warp = tid >> 5;
    const int hA = warp * 16 + (lane & 7);
    const int g  = lane >> 3;
    const int n0 = g * 7;

    ull accA[7], accB[7];
    #pragma unroll
    for (int k = 0; k < 7; k++) { accA[k] = 0ull; accB[k] = 0ull; }

    // W1 staging: thread loads row (tid>>3)+32*it, cols 4*(tid&7)..+3
    const int whr = tid >> 3;
    const int wcc = (tid & 7) * 4;
    const float* W1base = W1 + (size_t)whr * CIN + wcc;

    float4 pf[4];                         // register prefetch of next chunk
    #pragma unroll
    for (int it = 0; it < 4; it++)
        pf[it] = *reinterpret_cast<const float4*>(W1base + (size_t)it * 32 * CIN);

    #pragma unroll 1
    for (int ch = 0; ch < NCHUNK; ch++) {
        __syncthreads();   // previous chunk's reads done (and phase-1 stores visible)
        #pragma unroll
        for (int it = 0; it < 4; it++)
            *reinterpret_cast<float4*>(sBY + (whr + it * 32) * BPAD + wcc) = pf[it];
        if (ch + 1 < NCHUNK) {
            #pragma unroll
            for (int it = 0; it < 4; it++)
                pf[it] = *reinterpret_cast<const float4*>(W1base + (size_t)it * 32 * CIN
                                                          + (ch + 1) * CCH);
        }
        __syncthreads();   // chunk visible

        const float* sA  = sSrc + n0 * SPAD + ch * CCH;
        const float* wPA = sBY + hA * BPAD;
        #pragma unroll
        for (int c4 = 0; c4 < CCH / 4; c4++) {
            const ulonglong2 wa = *reinterpret_cast<const ulonglong2*>(wPA + c4 * 4);
            const ulonglong2 wb = *reinterpret_cast<const ulonglong2*>(wPA + 8 * BPAD + c4 * 4);
            #pragma unroll
            for (int k = 0; k < 7; k++) {
                if (g < 3 || k < 4) {     // n-slot valid (phase-uniform)
                    const ulonglong2 s2 =
                        *reinterpret_cast<const ulonglong2*>(sA + k * SPAD + c4 * 4);
                    fma2(accA[k], s2.x, wa.x);
                    fma2(accA[k], s2.y, wa.y);
                    fma2(accB[k], s2.x, wb.x);
                    fma2(accB[k], s2.y, wb.y);
                }
            }
        }
    }

    __syncthreads();       // done reading sBY as W1 -> reuse region as sY
    float* sY = sBY;
    #pragma unroll
    for (int k = 0; k < 7; k++) {
        if (g < 3 || k < 4) {
            const int n = n0 + k;
            sY[n * YPAD + hA]     = lo2(accA[k]) + hi2(accA[k]);
            sY[n * YPAD + hA + 8] = lo2(accB[k]) + hi2(accB[k]);
        }
    }
    __syncthreads();

    // ---- Phase 2.5: z[n] = sum_h W2[h]*y[n][h] (warp per n) ----
    for (int n = warp; n < NJ; n += 8) {
        const float* yr = sY + n * YPAD;
        float v = sW2[lane]      * yr[lane]
                + sW2[lane + 32] * yr[lane + 32]
                + sW2[lane + 64] * yr[lane + 64]
                + sW2[lane + 96] * yr[lane + 96];
        #pragma unroll
        for (int o = 16; o > 0; o >>= 1)
            v += __shfl_xor_sync(0xffffffffu, v, o);
        if (lane == 0) sZ[n] = v;
    }
    __syncthreads();

    // ---- Phase 3: 2x2 (i,j) register tiles, f32x2 math ----
    if (tid < 169) {                       // 13x13 tiles cover 25x25 (padded 26)
        const float alpha = alpha_p[0];
        const float c1 = 0.5f * (1.0f + alpha);
        const float c2 = 0.5f * (1.0f - alpha);
        const int ti = tid / 13, tj = tid - ti * 13;
        const int i0 = 2 * ti, j0 = 2 * tj;

        const ull NEG1  = 0xBF800000BF800000ull;   // (-1.0f, -1.0f)
        const ull AMASK = 0x7FFFFFFF7FFFFFFFull;   // abs mask

        ull a00 = 0, a01 = 0, a10 = 0, a11 = 0;
        const float* pi0 = sY + i0 * YPAD;
        const float* pj0 = sY + j0 * YPAD;

        #pragma unroll 8
        for (int h = 0; h < HID; h += 4) {
            const ulonglong2 w   = *reinterpret_cast<const ulonglong2*>(sW2 + h);
            const ulonglong2 vi0 = *reinterpret_cast<const ulonglong2*>(pi0 + h);
            const ulonglong2 vi1 = *reinterpret_cast<const ulonglong2*>(pi0 + YPAD + h);
            const ulonglong2 vj0 = *reinterpret_cast<const ulonglong2*>(pj0 + h);
            const ulonglong2 vj1 = *reinterpret_cast<const ulonglong2*>(pj0 + YPAD + h);
            ull d;
            // (0,0)
            d = vj0.x; fma2(d, vi0.x, NEG1); d &= AMASK; fma2(a00, d, w.x);
            d = vj0.y; fma2(d, vi0.y, NEG1); d &= AMASK; fma2(a00, d, w.y);
            // (0,1)
            d = vj1.x; fma2(d, vi0.x, NEG1); d &= AMASK; fma2(a01, d, w.x);
            d = vj1.y; fma2(d, vi0.y, NEG1); d &= AMASK; fma2(a01, d, w.y);
            // (1,0)
            d = vj0.x; fma2(d, vi1.x, NEG1); d &= AMASK; fma2(a10, d, w.x);
            d = vj0.y; fma2(d, vi1.y, NEG1); d &= AMASK; fma2(a10, d, w.y);
            // (1,1)
            d = vj1.x; fma2(d, vi1.x, NEG1); d &= AMASK; fma2(a11, d, w.x);
            d = vj1.y; fma2(d, vi1.y, NEG1); d &= AMASK; fma2(a11, d, w.y);
        }

        float* outB = out + (size_t)b * NJ * NJ;
        const int i1 = i0 + 1, j1 = j0 + 1;
        outB[i0 * NJ + j0] = c1 * (sZ[j0] - sZ[i0]) + c2 * (lo2(a00) + hi2(a00));
        if (j1 < NJ)
            outB[i0 * NJ + j1] = c1 * (sZ[j1] - sZ[i0]) + c2 * (lo2(a01) + hi2(a01));
        if (i1 < NJ) {
            outB[i1 * NJ + j0] = c1 * (sZ[j0] - sZ[i1]) + c2 * (lo2(a10) + hi2(a10));
            if (j1 < NJ)
                outB[i1 * NJ + j1] = c1 * (sZ[j1] - sZ[i1]) + c2 * (lo2(a11) + hi2(a11));
        }
    }
}

extern "C" void kernel_launch(void* const* d_in, const int* in_sizes, int n_in,
                              void* d_out, int out_size)
{
    // metadata order: src, heads, ends, pair_ids, W1, alpha, W2
    const float* src   = (const float*)d_in[0];
    const float* W1    = (const float*)d_in[4];
    const float* alpha = (const float*)d_in[5];
    const float* W2    = (const float*)d_in[6];
    float* out = (float*)d_out;

    const int batch = in_sizes[0] / (NJ * CIN);   // 256
    fused_edge_mlp_kernel<<<batch, 256>>>(src, W1, alpha, W2, out);
}

// round 5
// speedup vs baseline: 3.5038x; 1.0821x over previous
#include <cuda_runtime.h>
#include <cstdint>

// Problem constants (fixed by the dataset)
#define NJ     25
#define CIN    256
#define SPAD   260     // sSrc row stride (floats) — conflict-free n-broadcast
#define HID    128
#define BPAD   68      // W1 chunk buffer row stride (floats), [128][64]+4 pad
#define YPAD   132     // sY row stride
#define NCHUNK 4       // 4 chunks x (32 c per c-half x 2 halves)

#define BUFSZ     (HID * BPAD)            // 8704 floats per buffer
#define SSRC_OFF  (2 * BUFSZ)             // 17408
#define SW2_OFF   (SSRC_OFF + NJ * SPAD)  // 23908
#define SZ_OFF    (SW2_OFF + HID)         // 24036
#define SMEM_FLOATS (SZ_OFF + 32)         // 24068
#define SMEM_BYTES  (SMEM_FLOATS * 4)     // 96272 B -> 2 blocks/SM = 188 KB

typedef unsigned long long ull;

__device__ __forceinline__ void fma2(ull& d, ull a, ull b) {
    asm("fma.rn.f32x2 %0, %1, %2, %0;" : "+l"(d) : "l"(a), "l"(b));
}
__device__ __forceinline__ float lo2(ull v){ return __uint_as_float((unsigned)v); }
__device__ __forceinline__ float hi2(ull v){ return __uint_as_float((unsigned)(v >> 32)); }
__device__ __forceinline__ void cpasync16(uint32_t dst, const float* src) {
    asm volatile("cp.async.cg.shared.global [%0], [%1], 16;\n" :: "r"(dst), "l"(src));
}

// out[b,i,j] = c1*(z[j]-z[i]) + c2 * sum_h W2[h]*|y[b,j,h]-y[b,i,h]|
//   y = src @ W1^T (chain telescoping + linearity); z[n]=sum_h W2[h]y[n,h]
//   c1=(1+a)/2, c2=(1-a)/2  (PReLU = linear + abs)

__global__ __launch_bounds__(256, 2)
void fused_edge_mlp_kernel(const float* __restrict__ src,
                           const float* __restrict__ W1,
                           const float* __restrict__ alpha_p,
                           const float* __restrict__ W2,
                           float* __restrict__ out)
{
    extern __shared__ float smem[];
    float* sSrc = smem + SSRC_OFF;
    float* sW2  = smem + SW2_OFF;
    float* sZ   = smem + SZ_OFF;

    const int tid   = threadIdx.x;
    const int b     = blockIdx.x;
    const int lane  = tid & 31;
    const int warp  = tid >> 5;
    const int warpH = warp & 3;       // h-span [32*warpH, 32*warpH+32)
    const int warpC = warp >> 2;      // c-half [128*warpC, ...)
    const int q     = lane & 7;       // h sub-row
    const int g     = lane >> 3;      // n-group: n in [7g, 7g+7) (g=3: 4 n)
    const int n0    = g * 7;

    const uint32_t smemU32 =
        (uint32_t)__cvta_generic_to_shared(smem);

    // ---- issue cp.async staging for W1 chunk 0 into buf0 ----
    // warp wr, iter k: idx=wr*8+k in [0,64): window=idx>>5 (c-half),
    // rows 4*(idx&31)+(lane>>3), cols (lane&7)*4 within 32-c window.
    {
        #pragma unroll
        for (int k = 0; k < 8; k++) {
            const int idx    = warp * 8 + k;
            const int window = idx >> 5;
            const int row    = (idx & 31) * 4 + (lane >> 3);
            const int bcol   = window * 32 + (lane & 7) * 4;
            const int gcol   = window * 128 + 0 * 32 + (lane & 7) * 4;
            cpasync16(smemU32 + (uint32_t)(row * BPAD + bcol) * 4,
                      W1 + (size_t)row * CIN + gcol);
        }
        asm volatile("cp.async.commit_group;\n");
    }

    // ---- stage src[b] (coalesced loads, padded stores) + W2 ----
    {
        const float4* g4 = reinterpret_cast<const float4*>(src + (size_t)b * NJ * CIN);
        for (int i = tid; i < NJ * CIN / 4; i += 256) {
            const int n = i >> 6;
            const int c = i & 63;
            *reinterpret_cast<float4*>(sSrc + n * SPAD + c * 4) = g4[i];
        }
        if (tid < HID) sW2[tid] = W2[tid];
    }

    // ---- Phase 2: y = src @ W1^T, 7n x 4h register tile, c-split ----
    ull acc[7][4];
    #pragma unroll
    for (int k = 0; k < 7; k++)
        #pragma unroll
        for (int m = 0; m < 4; m++) acc[k][m] = 0ull;

    #pragma unroll 1
    for (int ch = 0; ch < NCHUNK; ch++) {
        float* bufc = smem + (ch & 1) * BUFSZ;
        if (ch + 1 < NCHUNK) {          // stage next chunk into other buffer
            const uint32_t dstbase = smemU32 + ((ch + 1) & 1) * (BUFSZ * 4);
            #pragma unroll
            for (int k = 0; k < 8; k++) {
                const int idx    = warp * 8 + k;
                const int window = idx >> 5;
                const int row    = (idx & 31) * 4 + (lane >> 3);
                const int bcol   = window * 32 + (lane & 7) * 4;
                const int gcol   = window * 128 + (ch + 1) * 32 + (lane & 7) * 4;
                cpasync16(dstbase + (uint32_t)(row * BPAD + bcol) * 4,
                          W1 + (size_t)row * CIN + gcol);
            }
            asm volatile("cp.async.commit_group;\n");
            asm volatile("cp.async.wait_group 1;\n");
        } else {
            asm volatile("cp.async.wait_group 0;\n");
        }
        __syncthreads();    // chunk ch visible to all; prior compute done

        const float* wrow = bufc + (32 * warpH + q) * BPAD + warpC * 32;
        const float* srow = sSrc + n0 * SPAD + warpC * 128 + ch * 32;

        #pragma unroll
        for (int c4i = 0; c4i < 8; c4i++) {
            const ulonglong2 wa = *reinterpret_cast<const ulonglong2*>(wrow + 4 * c4i);
            const ulonglong2 wb = *reinterpret_cast<const ulonglong2*>(wrow + 8  * BPAD + 4 * c4i);
            const ulonglong2 wc = *reinterpret_cast<const ulonglong2*>(wrow + 16 * BPAD + 4 * c4i);
            const ulonglong2 wd = *reinterpret_cast<const ulonglong2*>(wrow + 24 * BPAD + 4 * c4i);
            #pragma unroll
            for (int k = 0; k < 7; k++) {
                if (g < 3 || k < 4) {
                    const ulonglong2 s2 =
                        *reinterpret_cast<const ulonglong2*>(srow + k * SPAD + 4 * c4i);
                    fma2(acc[k][0], s2.x, wa.x); fma2(acc[k][0], s2.y, wa.y);
                    fma2(acc[k][1], s2.x, wb.x); fma2(acc[k][1], s2.y, wb.y);
                    fma2(acc[k][2], s2.x, wc.x); fma2(acc[k][2], s2.y, wc.y);
                    fma2(acc[k][3], s2.x, wd.x); fma2(acc[k][3], s2.y, wd.y);
                }
            }
        }
    }

    // ---- cross-half reduction into sY (reuse buf0 region) ----
    __syncthreads();                    // all reads of buffers done
    float* sY = smem;
    if (warpC == 0) {
        #pragma unroll
        for (int k = 0; k < 7; k++) {
            if (g < 3 || k < 4) {
                const int n = n0 + k;
                #pragma unroll
                for (int m = 0; m < 4; m++)
                    sY[n * YPAD + 32 * warpH + q + 8 * m] = lo2(acc[k][m]) + hi2(acc[k][m]);
            }
        }
    }
    __syncthreads();
    if (warpC == 1) {
        #pragma unroll
        for (int k = 0; k < 7; k++) {
            if (g < 3 || k < 4) {
                const int n = n0 + k;
                #pragma unroll
                for (int m = 0; m < 4; m++)
                    sY[n * YPAD + 32 * warpH + q + 8 * m] += lo2(acc[k][m]) + hi2(acc[k][m]);
            }
        }
    }
    __syncthreads();

    // ---- z[n] = sum_h W2[h]*y[n][h] (warp per n) ----
    for (int n = warp; n < NJ; n += 8) {
        const float* yr = sY + n * YPAD;
        float v = sW2[lane]      * yr[lane]
                + sW2[lane + 32] * yr[lane + 32]
                + sW2[lane + 64] * yr[lane + 64]
                + sW2[lane + 96] * yr[lane + 96];
        #pragma unroll
        for (int o = 16; o > 0; o >>= 1)
            v += __shfl_xor_sync(0xffffffffu, v, o);
        if (lane == 0) sZ[n] = v;
    }
    __syncthreads();

    // ---- Phase 3: j on lanes, i split across warps, 32-h chunks ----
    {
        const float alpha = alpha_p[0];
        const float c1 = 0.5f * (1.0f + alpha);
        const float c2 = 0.5f * (1.0f - alpha);
        const ull NEG1  = 0xBF800000BF800000ull;
        const ull AMASK = 0x7FFFFFFF7FFFFFFFull;

        ull accI[4] = {0ull, 0ull, 0ull, 0ull};
        const float* yjrow = sY + lane * YPAD;   // lanes 25-31 read garbage, unused

        #pragma unroll
        for (int hc = 0; hc < 4; hc++) {
            const int hb = hc * 32;
            ulonglong2 yj0 = *reinterpret_cast<const ulonglong2*>(yjrow + hb);
            ulonglong2 yj1 = *reinterpret_cast<const ulonglong2*>(yjrow + hb + 4);
            ulonglong2 yj2 = *reinterpret_cast<const ulonglong2*>(yjrow + hb + 8);
            ulonglong2 yj3 = *reinterpret_cast<const ulonglong2*>(yjrow + hb + 12);
            ulonglong2 yj4 = *reinterpret_cast<const ulonglong2*>(yjrow + hb + 16);
            ulonglong2 yj5 = *reinterpret_cast<const ulonglong2*>(yjrow + hb + 20);
            ulonglong2 yj6 = *reinterpret_cast<const ulonglong2*>(yjrow + hb + 24);
            ulonglong2 yj7 = *reinterpret_cast<const ulonglong2*>(yjrow + hb + 28);
            const ulonglong2 w0 = *reinterpret_cast<const ulonglong2*>(sW2 + hb);
            const ulonglong2 w1 = *reinterpret_cast<const ulonglong2*>(sW2 + hb + 4);
            const ulonglong2 w2q = *reinterpret_cast<const ulonglong2*>(sW2 + hb + 8);
            const ulonglong2 w3 = *reinterpret_cast<const ulonglong2*>(sW2 + hb + 12);
            const ulonglong2 w4 = *reinterpret_cast<const ulonglong2*>(sW2 + hb + 16);
            const ulonglong2 w5 = *reinterpret_cast<const ulonglong2*>(sW2 + hb + 20);
            const ulonglong2 w6 = *reinterpret_cast<const ulonglong2*>(sW2 + hb + 24);
            const ulonglong2 w7 = *reinterpret_cast<const ulonglong2*>(sW2 + hb + 28);

            #pragma unroll
            for (int t = 0; t < 4; t++) {
                const int i = warp + 8 * t;
                if (i < NJ) {
                    const float* yirow = sY + i * YPAD + hb;
                    const ulonglong2 yi0 = *reinterpret_cast<const ulonglong2*>(yirow);
                    const ulonglong2 yi1 = *reinterpret_cast<const ulonglong2*>(yirow + 4);
                    const ulonglong2 yi2 = *reinterpret_cast<const ulonglong2*>(yirow + 8);
                    const ulonglong2 yi3 = *reinterpret_cast<const ulonglong2*>(yirow + 12);
                    const ulonglong2 yi4 = *reinterpret_cast<const ulonglong2*>(yirow + 16);
                    const ulonglong2 yi5 = *reinterpret_cast<const ulonglong2*>(yirow + 20);
                    const ulonglong2 yi6 = *reinterpret_cast<const ulonglong2*>(yirow + 24);
                    const ulonglong2 yi7 = *reinterpret_cast<const ulonglong2*>(yirow + 28);
                    ull d;
                    d = yj0.x; fma2(d, yi0.x, NEG1); d &= AMASK; fma2(accI[t], d, w0.x);
                    d = yj0.y; fma2(d, yi0.y, NEG1); d &= AMASK; fma2(accI[t], d, w0.y);
                    d = yj1.x; fma2(d, yi1.x, NEG1); d &= AMASK; fma2(accI[t], d, w1.x);
                    d = yj1.y; fma2(d, yi1.y, NEG1); d &= AMASK; fma2(accI[t], d, w1.y);
                    d = yj2.x; fma2(d, yi2.x, NEG1); d &= AMASK; fma2(accI[t], d, w2q.x);
                    d = yj2.y; fma2(d, yi2.y, NEG1); d &= AMASK; fma2(accI[t], d, w2q.y);
                    d = yj3.x; fma2(d, yi3.x, NEG1); d &= AMASK; fma2(accI[t], d, w3.x);
                    d = yj3.y; fma2(d, yi3.y, NEG1); d &= AMASK; fma2(accI[t], d, w3.y);
                    d = yj4.x; fma2(d, yi4.x, NEG1); d &= AMASK; fma2(accI[t], d, w4.x);
                    d = yj4.y; fma2(d, yi4.y, NEG1); d &= AMASK; fma2(accI[t], d, w4.y);
                    d = yj5.x; fma2(d, yi5.x, NEG1); d &= AMASK; fma2(accI[t], d, w5.x);
                    d = yj5.y; fma2(d, yi5.y, NEG1); d &= AMASK; fma2(accI[t], d, w5.y);
                    d = yj6.x; fma2(d, yi6.x, NEG1); d &= AMASK; fma2(accI[t], d, w6.x);
                    d = yj6.y; fma2(d, yi6.y, NEG1); d &= AMASK; fma2(accI[t], d, w6.y);
                    d = yj7.x; fma2(d, yi7.x, NEG1); d &= AMASK; fma2(accI[t], d, w7.x);
                    d = yj7.y; fma2(d, yi7.y, NEG1); d &= AMASK; fma2(accI[t], d, w7.y);
                }
            }
        }

        float* outB = out + (size_t)b * NJ * NJ;
        if (lane < NJ) {
            const float zj = sZ[lane];
            #pragma unroll
            for (int t = 0; t < 4; t++) {
                const int i = warp + 8 * t;
                if (i < NJ)
                    outB[i * NJ + lane] =
                        c1 * (zj - sZ[i]) + c2 * (lo2(accI[t]) + hi2(accI[t]));
            }
        }
    }
}

extern "C" void kernel_launch(void* const* d_in, const int* in_sizes, int n_in,
                              void* d_out, int out_size)
{
    // metadata order: src, heads, ends, pair_ids, W1, alpha, W2
    const float* src   = (const float*)d_in[0];
    const float* W1    = (const float*)d_in[4];
    const float* alpha = (const float*)d_in[5];
    const float* W2    = (const float*)d_in[6];
    float* out = (float*)d_out;

    cudaFuncSetAttribute(fused_edge_mlp_kernel,
                         cudaFuncAttributeMaxDynamicSharedMemorySize, SMEM_BYTES);

    const int batch = in_sizes[0] / (NJ * CIN);   // 256
    fused_edge_mlp_kernel<<<batch, 256, SMEM_BYTES>>>(src, W1, alpha, W2, out);
}